// round 1
// baseline (speedup 1.0000x reference)
#include <cuda_runtime.h>
#include <math.h>

#define BATCH 64
#define TSEQ  256
#define DIN   256
#define HDIM  512
#define G4H   2048
#define NCTA  32      // recurrence CTAs; each owns 16 hidden units
#define UPC   16      // units per CTA

// ---------------- scratch (device globals; no allocation allowed) ----------
__device__ float g_G[(size_t)BATCH * TSEQ * G4H];   // precomputed Wih@x + b_ih + b_hh
__device__ float g_h[2][HDIM];                      // double-buffered hidden state
__device__ int   g_flags[NCTA];                     // per-CTA epoch counters
__device__ float g_hall[BATCH * HDIM];              // h at end of each sample
__device__ float g_z1[BATCH * 1024];
__device__ float g_z2[BATCH * 1024];

// ---------------- init: reset state every graph replay ---------------------
__global__ void init_kernel() {
    int tid = threadIdx.x;
    if (tid < HDIM) { g_h[0][tid] = 0.f; g_h[1][tid] = 0.f; }
    if (tid < NCTA) g_flags[tid] = -1;
}

// ---------------- X projection GEMM: G = X @ Wih^T + (b_ih + b_hh) ---------
// C[16384, 2048], A=X[16384,256], B=Wih[2048,256] (both K-major).
#define BM 64
#define BN 64
#define BK 32
__global__ void __launch_bounds__(256) xproj_kernel(
    const float* __restrict__ X, const float* __restrict__ Wih,
    const float* __restrict__ bih, const float* __restrict__ bhh,
    const int* __restrict__ starts, const int* __restrict__ ends)
{
    const int bn = blockIdx.x;           // col tile
    const int bm = blockIdx.y;           // row tile
    const int R0 = bm * BM;
    const int b  = R0 >> 8;              // 256 rows per sample
    const int t0 = R0 & 255;

    // activity skip: tile covers t in [t0, t0+63]; active iff overlaps (start, end]
    const int st = starts[b], en = ends[b];
    const int tlo = max(t0, st + 1);
    const int thi = min(t0 + BM - 1, en);
    if (tlo > thi) return;

    __shared__ float As[BK][BM];
    __shared__ float Bs[BK][BN];

    const int tid = threadIdx.x;
    const int tx = tid & 15, ty = tid >> 4;

    float acc[4][4] = {};

    for (int k0 = 0; k0 < DIN; k0 += BK) {
        #pragma unroll
        for (int i = 0; i < 2; i++) {
            int idx = tid + i * 256;
            int row = idx >> 3, k4 = idx & 7;
            float4 v = *(const float4*)(X + (size_t)(R0 + row) * DIN + k0 + k4 * 4);
            As[k4*4+0][row] = v.x; As[k4*4+1][row] = v.y;
            As[k4*4+2][row] = v.z; As[k4*4+3][row] = v.w;
            float4 u = *(const float4*)(Wih + (size_t)(bn * BN + row) * DIN + k0 + k4 * 4);
            Bs[k4*4+0][row] = u.x; Bs[k4*4+1][row] = u.y;
            Bs[k4*4+2][row] = u.z; Bs[k4*4+3][row] = u.w;
        }
        __syncthreads();
        #pragma unroll
        for (int kk = 0; kk < BK; kk++) {
            float a[4], bb[4];
            #pragma unroll
            for (int p = 0; p < 4; p++) a[p]  = As[kk][ty * 4 + p];
            #pragma unroll
            for (int q = 0; q < 4; q++) bb[q] = Bs[kk][tx * 4 + q];
            #pragma unroll
            for (int p = 0; p < 4; p++)
                #pragma unroll
                for (int q = 0; q < 4; q++)
                    acc[p][q] += a[p] * bb[q];
        }
        __syncthreads();
    }

    #pragma unroll
    for (int q = 0; q < 4; q++) {
        int col = bn * BN + tx * 4 + q;
        float bias = bih[col] + bhh[col];
        #pragma unroll
        for (int p = 0; p < 4; p++) {
            int row = R0 + ty * 4 + p;
            g_G[(size_t)row * G4H + col] = acc[p][q] + bias;
        }
    }
}

// ---------------- sequential LSTM recurrence (persistent, 32 CTAs) ---------
// CTA s owns hidden units [16s, 16s+16). Its 64 gate rows (i,f,g,o for those
// units) of W_hh live in registers: warp w holds local rows 4w..4w+3, lane l
// holds columns {l + 32j, j=0..15}. Per-step h exchange via L2 double buffer.
__global__ void __launch_bounds__(512, 1) recur_kernel(
    const float* __restrict__ Whh,
    const int* __restrict__ starts, const int* __restrict__ ends)
{
    const int s = blockIdx.x;
    const int tid = threadIdx.x;
    const int w = tid >> 5, l = tid & 31;

    __shared__ float h_sm[HDIM];
    __shared__ float gsum[64];
    __shared__ float c_sm[UPC];

    // register-resident W_hh slice: local row lr = gate*16 + ul
    float Wreg[4][16];
    #pragma unroll
    for (int p = 0; p < 4; p++) {
        int lr = 4 * w + p;
        int gate = lr >> 4, ul = lr & 15;
        const float* wr = Whh + (size_t)(gate * HDIM + s * UPC + ul) * HDIM;
        #pragma unroll
        for (int j = 0; j < 16; j++) Wreg[p][j] = wr[l + 32 * j];
    }
    if (tid < UPC) c_sm[tid] = 0.f;
    __syncthreads();

    volatile int* vflags = (volatile int*)g_flags;
    int step = 0;

    for (int b = 0; b < BATCH; b++) {
        const int st = starts[b], en = ends[b];
        for (int t = st + 1; t <= en; t++) {
            // prefetch this step's input-projection gates (latency hidden by spin+matvec)
            float Gi = 0.f, Gf = 0.f, Gg = 0.f, Go = 0.f;
            if (tid < UPC) {
                const float* Grow = g_G + (size_t)(b * TSEQ + t) * G4H;
                int col = s * UPC + tid;
                Gi = Grow[col];
                Gf = Grow[HDIM + col];
                Gg = Grow[2 * HDIM + col];
                Go = Grow[3 * HDIM + col];
            }

            // wait for all producers of step-1
            if (tid < NCTA) {
                while (vflags[tid] < step - 1) { }
                __threadfence();
            }
            __syncthreads();

            // load h^{step-1} (L1-bypass: buffer addresses alias every 2 steps)
            const float* hbuf = g_h[(step + 1) & 1];
            h_sm[tid] = __ldcg(&hbuf[tid]);
            __syncthreads();

            // matvec: 4 gate-row partials per thread
            float a0 = 0.f, a1 = 0.f, a2 = 0.f, a3 = 0.f;
            #pragma unroll
            for (int j = 0; j < 16; j++) {
                float hv = h_sm[l + 32 * j];
                a0 += Wreg[0][j] * hv;
                a1 += Wreg[1][j] * hv;
                a2 += Wreg[2][j] * hv;
                a3 += Wreg[3][j] * hv;
            }
            #pragma unroll
            for (int off = 16; off >= 1; off >>= 1) {
                a0 += __shfl_xor_sync(0xffffffffu, a0, off);
                a1 += __shfl_xor_sync(0xffffffffu, a1, off);
                a2 += __shfl_xor_sync(0xffffffffu, a2, off);
                a3 += __shfl_xor_sync(0xffffffffu, a3, off);
            }
            if (l == 0) {
                gsum[4 * w + 0] = a0;
                gsum[4 * w + 1] = a1;
                gsum[4 * w + 2] = a2;
                gsum[4 * w + 3] = a3;
            }
            __syncthreads();

            // gate combine for this CTA's 16 units
            if (tid < UPC) {
                float gi = Gi + gsum[0 * UPC + tid];
                float gf = Gf + gsum[1 * UPC + tid];
                float gg = Gg + gsum[2 * UPC + tid];
                float go = Go + gsum[3 * UPC + tid];
                float ii = 1.f / (1.f + expf(-gi));
                float ff = 1.f / (1.f + expf(-gf));
                float oo = 1.f / (1.f + expf(-go));
                float c  = ff * c_sm[tid] + ii * tanhf(gg);
                float hn = oo * tanhf(c);
                c_sm[tid] = c;
                __stcg(&g_h[step & 1][s * UPC + tid], hn);
                if (t == en) g_hall[b * HDIM + s * UPC + tid] = hn;
            }
            __syncthreads();
            if (tid == 0) {
                __threadfence();
                vflags[s] = step;   // release this step's h chunk
            }
            step++;
        }
    }
}

// ---------------- MLP head ------------------------------------------------
__global__ void __launch_bounds__(512) mlp1_kernel(
    const float* __restrict__ W1, const float* __restrict__ b1)
{
    const int b = blockIdx.x, tid = threadIdx.x;
    __shared__ float hs[HDIM];
    hs[tid] = g_hall[b * HDIM + tid];
    __syncthreads();
    for (int o = tid; o < 1024; o += 512) {
        const float4* wr = (const float4*)(W1 + (size_t)o * HDIM);
        float acc = 0.f;
        #pragma unroll 8
        for (int k = 0; k < HDIM / 4; k++) {
            float4 v = wr[k];
            acc += v.x * hs[4*k] + v.y * hs[4*k+1] + v.z * hs[4*k+2] + v.w * hs[4*k+3];
        }
        acc += b1[o];
        g_z1[b * 1024 + o] = fmaxf(acc, 0.f);
    }
}

__global__ void __launch_bounds__(512) mlp2_kernel(
    const float* __restrict__ W2, const float* __restrict__ b2)
{
    const int b = blockIdx.x, tid = threadIdx.x;
    __shared__ float zs[1024];
    zs[tid] = g_z1[b * 1024 + tid];
    zs[tid + 512] = g_z1[b * 1024 + tid + 512];
    __syncthreads();
    for (int o = tid; o < 1024; o += 512) {
        const float4* wr = (const float4*)(W2 + (size_t)o * 1024);
        float acc = 0.f;
        #pragma unroll 8
        for (int k = 0; k < 1024 / 4; k++) {
            float4 v = wr[k];
            acc += v.x * zs[4*k] + v.y * zs[4*k+1] + v.z * zs[4*k+2] + v.w * zs[4*k+3];
        }
        acc += b2[o];
        g_z2[b * 1024 + o] = fmaxf(acc, 0.f);
    }
}

__global__ void __launch_bounds__(256) mlp3_kernel(
    const float* __restrict__ W3, const float* __restrict__ b3,
    const float* __restrict__ tv, float* __restrict__ out, int out_size)
{
    const int b = blockIdx.x, tid = threadIdx.x;
    const float* z = g_z2 + (size_t)b * 1024;
    float acc = 0.f;
    for (int k = tid; k < 1024; k += 256) acc += W3[k] * z[k];
    #pragma unroll
    for (int off = 16; off >= 1; off >>= 1) acc += __shfl_xor_sync(0xffffffffu, acc, off);
    __shared__ float ws[8];
    if ((tid & 31) == 0) ws[tid >> 5] = acc;
    __syncthreads();
    if (tid == 0) {
        float ssum = 0.f;
        #pragma unroll
        for (int i = 0; i < 8; i++) ssum += ws[i];
        out[b] = 1.f / (1.f + expf(-(ssum + b3[0])));
        if (64 + b < out_size) out[64 + b] = tv[b];   // pass-through true_vals
    }
}

// ---------------- launch --------------------------------------------------
extern "C" void kernel_launch(void* const* d_in, const int* in_sizes, int n_in,
                              void* d_out, int out_size)
{
    const float* x      = (const float*)d_in[0];
    const float* tv     = (const float*)d_in[1];
    const float* W_ih   = (const float*)d_in[2];
    const float* W_hh   = (const float*)d_in[3];
    const float* b_ih   = (const float*)d_in[4];
    const float* b_hh   = (const float*)d_in[5];
    const float* W1     = (const float*)d_in[6];
    const float* b1     = (const float*)d_in[7];
    const float* W2     = (const float*)d_in[8];
    const float* b2     = (const float*)d_in[9];
    const float* W3     = (const float*)d_in[10];
    const float* b3     = (const float*)d_in[11];
    const int*   starts = (const int*)d_in[12];
    const int*   ends   = (const int*)d_in[13];
    float* out = (float*)d_out;

    init_kernel<<<1, 512>>>();

    dim3 ggrid(G4H / BN, (BATCH * TSEQ) / BM);
    xproj_kernel<<<ggrid, 256>>>(x, W_ih, b_ih, b_hh, starts, ends);

    recur_kernel<<<NCTA, 512>>>(W_hh, starts, ends);

    mlp1_kernel<<<BATCH, 512>>>(W1, b1);
    mlp2_kernel<<<BATCH, 512>>>(W2, b2);
    mlp3_kernel<<<BATCH, 256>>>(W3, b3, tv, out, out_size);
}

// round 3
// speedup vs baseline: 1.9222x; 1.9222x over previous
#include <cuda_runtime.h>
#include <math.h>

#define BATCH 64
#define TSEQ  256
#define DIN   256
#define HDIM  512
#define G4H   2048
#define NCTA  32      // recurrence CTAs; each owns 16 hidden units
#define UPC   16      // units per CTA

// ---------------- scratch (device globals; no allocation allowed) ----------
__device__ float g_G[(size_t)BATCH * TSEQ * G4H];       // Wih@x + b_ih + b_hh
__device__ unsigned long long g_hpair[2][HDIM];         // (tag<<32)|h  double buffer
__device__ float g_hall[BATCH * HDIM];                  // h at end of each sample
__device__ float g_z1[BATCH * 1024];
__device__ float g_z2[BATCH * 1024];

// ---------------- fast activations (err ~1e-6, budget 1e-3) ----------------
__device__ __forceinline__ float sig_f(float x) {
    return __fdividef(1.f, 1.f + __expf(-x));
}
__device__ __forceinline__ float tanh_f(float x) {
    // 1 - 2/(e^{2x}+1): saturates correctly at +-1
    return 1.f - 2.f * __fdividef(1.f, __expf(2.f * x) + 1.f);
}

// ---------------- init: reset state every graph replay ---------------------
__global__ void init_kernel() {
    int tid = threadIdx.x;
    if (tid < HDIM) {
        // tag -1 in both buffers; buffer 1 (parity of step -1) holds h0 = 0
        unsigned long long p = ((unsigned long long)(unsigned)(-1) << 32);
        g_hpair[0][tid] = p;
        g_hpair[1][tid] = p;   // value bits 0 => h = 0.0f
    }
}

// ---------------- X projection GEMM: G = X @ Wih^T + (b_ih + b_hh) ---------
#define BM 64
#define BN 64
#define BK 32
__global__ void __launch_bounds__(256) xproj_kernel(
    const float* __restrict__ X, const float* __restrict__ Wih,
    const float* __restrict__ bih, const float* __restrict__ bhh,
    const int* __restrict__ starts, const int* __restrict__ ends)
{
    const int bn = blockIdx.x;
    const int bm = blockIdx.y;
    const int R0 = bm * BM;
    const int b  = R0 >> 8;
    const int t0 = R0 & 255;

    // skip tiles with no active timesteps: active iff t in (start, end]
    const int st = starts[b], en = ends[b];
    if (max(t0, st + 1) > min(t0 + BM - 1, en)) return;

    __shared__ float As[BK][BM];
    __shared__ float Bs[BK][BN];

    const int tid = threadIdx.x;
    const int tx = tid & 15, ty = tid >> 4;
    float acc[4][4] = {};

    for (int k0 = 0; k0 < DIN; k0 += BK) {
        #pragma unroll
        for (int i = 0; i < 2; i++) {
            int idx = tid + i * 256;
            int row = idx >> 3, k4 = idx & 7;
            float4 v = *(const float4*)(X + (size_t)(R0 + row) * DIN + k0 + k4 * 4);
            As[k4*4+0][row] = v.x; As[k4*4+1][row] = v.y;
            As[k4*4+2][row] = v.z; As[k4*4+3][row] = v.w;
            float4 u = *(const float4*)(Wih + (size_t)(bn * BN + row) * DIN + k0 + k4 * 4);
            Bs[k4*4+0][row] = u.x; Bs[k4*4+1][row] = u.y;
            Bs[k4*4+2][row] = u.z; Bs[k4*4+3][row] = u.w;
        }
        __syncthreads();
        #pragma unroll
        for (int kk = 0; kk < BK; kk++) {
            float a[4], bb[4];
            #pragma unroll
            for (int p = 0; p < 4; p++) a[p]  = As[kk][ty * 4 + p];
            #pragma unroll
            for (int q = 0; q < 4; q++) bb[q] = Bs[kk][tx * 4 + q];
            #pragma unroll
            for (int p = 0; p < 4; p++)
                #pragma unroll
                for (int q = 0; q < 4; q++)
                    acc[p][q] += a[p] * bb[q];
        }
        __syncthreads();
    }

    #pragma unroll
    for (int q = 0; q < 4; q++) {
        int col = bn * BN + tx * 4 + q;
        float bias = bih[col] + bhh[col];
        #pragma unroll
        for (int p = 0; p < 4; p++) {
            int row = R0 + ty * 4 + p;
            g_G[(size_t)row * G4H + col] = acc[p][q] + bias;
        }
    }
}

// ---------------- sequential LSTM recurrence (persistent, 32 CTAs) ---------
// CTA s owns hidden units [16s, 16s+16). W_hh slice register-resident.
// Per-step exchange: each h element is an 8B (tag|value) word in L2; one
// relaxed 8B store publishes it, consumers poll the word itself. Single L2
// round-trip per step, no fences. Skew <= 1 step => 2 buffers suffice.
__global__ void __launch_bounds__(512, 1) recur_kernel(
    const float* __restrict__ Whh,
    const int* __restrict__ starts, const int* __restrict__ ends)
{
    const int s = blockIdx.x;
    const int tid = threadIdx.x;
    const int w = tid >> 5, l = tid & 31;

    __shared__ float h_sm[HDIM];
    __shared__ float gsum[64];

    // register-resident W_hh slice: warp w holds local rows 4w..4w+3
    float Wreg[4][16];
    #pragma unroll
    for (int p = 0; p < 4; p++) {
        int lr = 4 * w + p;
        int gate = lr >> 4, ul = lr & 15;
        const float* wr = Whh + (size_t)(gate * HDIM + s * UPC + ul) * HDIM;
        #pragma unroll
        for (int j = 0; j < 16; j++) Wreg[p][j] = wr[l + 32 * j];
    }

    float creg = 0.f;           // cell state for unit (s*16 + tid), tid<16
    int step = 0;

    for (int b = 0; b < BATCH; b++) {
        const int st = starts[b], en = ends[b];
        for (int t = st + 1; t <= en; t++) {
            // prefetch this step's input-projection gate values
            float Gi = 0.f, Gf = 0.f, Gg = 0.f, Go = 0.f;
            if (tid < UPC) {
                const float* Grow = g_G + (size_t)(b * TSEQ + t) * G4H;
                int col = s * UPC + tid;
                Gi = __ldg(Grow + col);
                Gf = __ldg(Grow + HDIM + col);
                Gg = __ldg(Grow + 2 * HDIM + col);
                Go = __ldg(Grow + 3 * HDIM + col);
            }

            // poll my h element of step-1 (tag check == data valid)
            {
                const unsigned long long* src = &g_hpair[(step + 1) & 1][tid];
                const int expect = step - 1;
                unsigned long long v;
                do {
                    asm volatile("ld.relaxed.gpu.global.b64 %0, [%1];"
                                 : "=l"(v) : "l"(src) : "memory");
                } while ((int)(v >> 32) != expect);
                h_sm[tid] = __uint_as_float((unsigned)v);
            }
            __syncthreads();

            // matvec: 4 gate-row partials per thread
            float a0 = 0.f, a1 = 0.f, a2 = 0.f, a3 = 0.f;
            #pragma unroll
            for (int j = 0; j < 16; j++) {
                float hv = h_sm[l + 32 * j];
                a0 += Wreg[0][j] * hv;
                a1 += Wreg[1][j] * hv;
                a2 += Wreg[2][j] * hv;
                a3 += Wreg[3][j] * hv;
            }
            #pragma unroll
            for (int off = 16; off >= 1; off >>= 1) {
                a0 += __shfl_xor_sync(0xffffffffu, a0, off);
                a1 += __shfl_xor_sync(0xffffffffu, a1, off);
                a2 += __shfl_xor_sync(0xffffffffu, a2, off);
                a3 += __shfl_xor_sync(0xffffffffu, a3, off);
            }
            if (l == 0) {
                gsum[4 * w + 0] = a0;
                gsum[4 * w + 1] = a1;
                gsum[4 * w + 2] = a2;
                gsum[4 * w + 3] = a3;
            }
            __syncthreads();

            // gate combine + publish (16 owner threads)
            if (tid < UPC) {
                float gi = Gi + gsum[0 * UPC + tid];
                float gf = Gf + gsum[1 * UPC + tid];
                float gg = Gg + gsum[2 * UPC + tid];
                float go = Go + gsum[3 * UPC + tid];
                float c  = sig_f(gf) * creg + sig_f(gi) * tanh_f(gg);
                float hn = sig_f(go) * tanh_f(c);
                creg = c;
                unsigned long long pv =
                    ((unsigned long long)(unsigned)step << 32) | __float_as_uint(hn);
                asm volatile("st.relaxed.gpu.global.b64 [%0], %1;"
                             :: "l"(&g_hpair[step & 1][s * UPC + tid]), "l"(pv)
                             : "memory");
                if (t == en) g_hall[b * HDIM + s * UPC + tid] = hn;
            }
            step++;
        }
    }
}

// ---------------- MLP head: C[64,N] = relu(A[64,K] @ W[N,K]^T + b) ---------
// LAYER 0: A=g_hall (K=512) -> g_z1;  LAYER 1: A=g_z1 (K=1024) -> g_z2.
// Templated on layer to reference device globals directly (no
// cudaGetSymbolAddress under graph capture).
template<int LAYER>
__global__ void __launch_bounds__(256) mlp_gemm_kernel(
    const float* __restrict__ W, const float* __restrict__ bias)
{
    const int K = (LAYER == 0) ? HDIM : 1024;
    const float* A = (LAYER == 0) ? g_hall : g_z1;
    float* C = (LAYER == 0) ? g_z1 : g_z2;
    const int N = 1024;

    const int bn = blockIdx.x;
    __shared__ float As[BK][BM];
    __shared__ float Bs[BK][BN];

    const int tid = threadIdx.x;
    const int tx = tid & 15, ty = tid >> 4;
    float acc[4][4] = {};

    for (int k0 = 0; k0 < K; k0 += BK) {
        #pragma unroll
        for (int i = 0; i < 2; i++) {
            int idx = tid + i * 256;
            int row = idx >> 3, k4 = idx & 7;
            float4 v = *(const float4*)(A + (size_t)row * K + k0 + k4 * 4);
            As[k4*4+0][row] = v.x; As[k4*4+1][row] = v.y;
            As[k4*4+2][row] = v.z; As[k4*4+3][row] = v.w;
            float4 u = *(const float4*)(W + (size_t)(bn * BN + row) * K + k0 + k4 * 4);
            Bs[k4*4+0][row] = u.x; Bs[k4*4+1][row] = u.y;
            Bs[k4*4+2][row] = u.z; Bs[k4*4+3][row] = u.w;
        }
        __syncthreads();
        #pragma unroll
        for (int kk = 0; kk < BK; kk++) {
            float a[4], bb[4];
            #pragma unroll
            for (int p = 0; p < 4; p++) a[p]  = As[kk][ty * 4 + p];
            #pragma unroll
            for (int q = 0; q < 4; q++) bb[q] = Bs[kk][tx * 4 + q];
            #pragma unroll
            for (int p = 0; p < 4; p++)
                #pragma unroll
                for (int q = 0; q < 4; q++)
                    acc[p][q] += a[p] * bb[q];
        }
        __syncthreads();
    }

    #pragma unroll
    for (int q = 0; q < 4; q++) {
        int col = bn * BN + tx * 4 + q;
        float bv = bias[col];
        #pragma unroll
        for (int p = 0; p < 4; p++) {
            int row = ty * 4 + p;
            C[(size_t)row * N + col] = fmaxf(acc[p][q] + bv, 0.f);
        }
    }
}

__global__ void __launch_bounds__(256) mlp3_kernel(
    const float* __restrict__ W3, const float* __restrict__ b3,
    const float* __restrict__ tv, float* __restrict__ out, int out_size)
{
    const int b = blockIdx.x, tid = threadIdx.x;
    const float* z = g_z2 + (size_t)b * 1024;
    float acc = 0.f;
    for (int k = tid; k < 1024; k += 256) acc += W3[k] * z[k];
    #pragma unroll
    for (int off = 16; off >= 1; off >>= 1) acc += __shfl_xor_sync(0xffffffffu, acc, off);
    __shared__ float ws[8];
    if ((tid & 31) == 0) ws[tid >> 5] = acc;
    __syncthreads();
    if (tid == 0) {
        float ssum = 0.f;
        #pragma unroll
        for (int i = 0; i < 8; i++) ssum += ws[i];
        out[b] = 1.f / (1.f + expf(-(ssum + b3[0])));
        if (64 + b < out_size) out[64 + b] = tv[b];   // pass-through true_vals
    }
}

// ---------------- launch --------------------------------------------------
extern "C" void kernel_launch(void* const* d_in, const int* in_sizes, int n_in,
                              void* d_out, int out_size)
{
    const float* x      = (const float*)d_in[0];
    const float* tv     = (const float*)d_in[1];
    const float* W_ih   = (const float*)d_in[2];
    const float* W_hh   = (const float*)d_in[3];
    const float* b_ih   = (const float*)d_in[4];
    const float* b_hh   = (const float*)d_in[5];
    const float* W1     = (const float*)d_in[6];
    const float* b1     = (const float*)d_in[7];
    const float* W2     = (const float*)d_in[8];
    const float* b2     = (const float*)d_in[9];
    const float* W3     = (const float*)d_in[10];
    const float* b3     = (const float*)d_in[11];
    const int*   starts = (const int*)d_in[12];
    const int*   ends   = (const int*)d_in[13];
    float* out = (float*)d_out;

    init_kernel<<<1, 512>>>();

    dim3 ggrid(G4H / BN, (BATCH * TSEQ) / BM);
    xproj_kernel<<<ggrid, 256>>>(x, W_ih, b_ih, b_hh, starts, ends);

    recur_kernel<<<NCTA, 512>>>(W_hh, starts, ends);

    mlp_gemm_kernel<0><<<16, 256>>>(W1, b1);
    mlp_gemm_kernel<1><<<16, 256>>>(W2, b2);
    mlp3_kernel<<<BATCH, 256>>>(W3, b3, tv, out, out_size);
}